// round 8
// baseline (speedup 1.0000x reference)
#include <cuda_runtime.h>
#include <cuda_bf16.h>
#include <math.h>
#include <stdint.h>

// Problem sizes
#define BB   128
#define TT   256
#define HH   512
#define G4   2048   // 4*H

// ---------------- scratch (static device memory; no allocations) ----------------
__device__ uint32_t g_xtf[(size_t)BB * TT * HH];              // x in tf32, [b][t][h]
__device__ uint32_t g_Wxtf[(size_t)2 * 2 * HH * G4];          // [l][d][k][n] tf32
__device__ uint32_t g_Whtf[(size_t)2 * 2 * HH * G4];          // [l][d][k][n] tf32
__device__ float    g_xproj[(size_t)2 * TT * BB * G4];        // [d][s][b][gate] fp32
__device__ uint32_t g_hbuf[(size_t)2 * TT * BB * HH];         // layer0 h out, tf32, [d][s][b][j]
__device__ uint32_t g_h[(size_t)2 * 2 * BB * HH];             // [parity][d][b][j] tf32
__device__ float    g_c[(size_t)2 * BB * HH];                 // [d][b][j] fp32

// ---------------- helpers ----------------
__device__ __forceinline__ uint32_t f2tf(float x) {
    uint32_t r;
    asm("cvt.rna.tf32.f32 %0, %1;" : "=r"(r) : "f"(x));
    return r;
}

__device__ __forceinline__ void mma_tf32(float acc[4], const uint32_t a[4], const uint32_t b[2]) {
    asm volatile(
        "mma.sync.aligned.m16n8k8.row.col.f32.tf32.tf32.f32 "
        "{%0,%1,%2,%3}, {%4,%5,%6,%7}, {%8,%9}, {%0,%1,%2,%3};\n"
        : "+f"(acc[0]), "+f"(acc[1]), "+f"(acc[2]), "+f"(acc[3])
        : "r"(a[0]), "r"(a[1]), "r"(a[2]), "r"(a[3]), "r"(b[0]), "r"(b[1]));
}

__device__ __forceinline__ void cp16(uint32_t* smem_ptr, const void* gptr) {
    uint32_t s = (uint32_t)__cvta_generic_to_shared(smem_ptr);
    asm volatile("cp.async.cg.shared.global [%0], [%1], 16;\n" :: "r"(s), "l"(gptr));
}
__device__ __forceinline__ void cp_commit() { asm volatile("cp.async.commit_group;\n"); }
template <int N>
__device__ __forceinline__ void cp_wait() { asm volatile("cp.async.wait_group %0;\n" :: "n"(N)); }

// Warp tile 32x32, one k8 slab. A smem row stride = 36 (BK=32 + 4 pad),
// B smem row stride = 68 (BN=64 + 4 pad). Both conflict-free for frag loads.
__device__ __forceinline__ void wtile_k8(const uint32_t* __restrict__ As,
                                         const uint32_t* __restrict__ Bs,
                                         int kk, int wm, int wn, int grp, int t4,
                                         float acc[2][4][4]) {
    uint32_t a[2][4], bf[4][2];
#pragma unroll
    for (int mt = 0; mt < 2; mt++) {
        const uint32_t* Ar = As + (wm + mt * 16 + grp) * 36 + kk + t4;
        a[mt][0] = Ar[0];          // (row g,   k t4)
        a[mt][1] = Ar[8 * 36];     // (row g+8, k t4)
        a[mt][2] = Ar[4];          // (row g,   k t4+4)
        a[mt][3] = Ar[8 * 36 + 4]; // (row g+8, k t4+4)
    }
#pragma unroll
    for (int nt = 0; nt < 4; nt++) {
        const uint32_t* Br = Bs + (kk + t4) * 68 + wn + nt * 8 + grp;
        bf[nt][0] = Br[0];        // (k t4,   n grp)
        bf[nt][1] = Br[4 * 68];   // (k t4+4, n grp)
    }
#pragma unroll
    for (int mt = 0; mt < 2; mt++)
#pragma unroll
        for (int nt = 0; nt < 4; nt++) mma_tf32(acc[mt][nt], a[mt], bf[nt]);
}

// ---------------- pre-convert fp32 -> tf32 ----------------
__global__ void k_preconvert(const float* __restrict__ x,
                             const float* __restrict__ Wx,
                             const float* __restrict__ Wh) {
    int stride = gridDim.x * blockDim.x;
    int i0 = blockIdx.x * blockDim.x + threadIdx.x;
    for (int i = i0; i < BB * TT * HH; i += stride) g_xtf[i] = f2tf(x[i]);
    for (int i = i0; i < 2 * 2 * HH * G4; i += stride) {
        g_Wxtf[i] = f2tf(Wx[i]);
        g_Whtf[i] = f2tf(Wh[i]);
    }
}

// ---------------- zero h(parity0) and c ----------------
__global__ void k_zero() {
    int i = blockIdx.x * blockDim.x + threadIdx.x;
    int n = 2 * BB * HH;
    if (i < n) {
        g_h[i] = 0u;   // parity 0 block is the first 2*128*512 entries
        g_c[i] = 0.f;
    }
}

// ---------------- input projection: xproj = A * Wx + bias ----------------
// Grid: (32 n-tiles of 64, 256 s, 2 dirs). 256 threads, 8 warps (4M x 2N).
// CTA tile: 128(M=batch) x 64(N), K=512 in 16 chunks of 32, double-buffered cp.async.
__global__ void __launch_bounds__(256) k_proj(int layer, const float* __restrict__ bias_all) {
    extern __shared__ uint32_t smp[];
    uint32_t* Asb[2] = { smp, smp + 4608 };             // 128*36 each
    uint32_t* Bsb[2] = { smp + 9216, smp + 11392 };     // 32*68 each

    const int tid = threadIdx.x, lane = tid & 31, warp = tid >> 5;
    const int grp = lane >> 2, t4 = lane & 3;
    const int wm = (warp & 3) * 32, wn = (warp >> 2) * 32;
    const int d = blockIdx.z, sIdx = blockIdx.y, n0 = blockIdx.x * 64;
    const int t_act = d ? (TT - 1 - sIdx) : sIdx;

    const uint32_t* Wb = g_Wxtf + ((size_t)(layer * 2 + d) * HH) * G4;

    float acc[2][4][4];
#pragma unroll
    for (int a = 0; a < 2; a++)
#pragma unroll
        for (int b = 0; b < 4; b++)
#pragma unroll
            for (int c = 0; c < 4; c++) acc[a][b][c] = 0.f;

    auto issue = [&](int kc, int buf) {
        int k0 = kc * 32;
#pragma unroll
        for (int i = 0; i < 4; i++) {                    // A: 128 rows x 32 k = 1024 vec16
            int v = tid + i * 256;
            int r = v >> 3, kcol = (v & 7) * 4;
            const uint32_t* src;
            if (layer == 0)
                src = g_xtf + ((size_t)r * TT + t_act) * HH + k0 + kcol;
            else
                src = g_hbuf + ((size_t)(d * (TT * BB) + sIdx * BB + r)) * HH + k0 + kcol;
            cp16(Asb[buf] + r * 36 + kcol, src);
        }
#pragma unroll
        for (int i = 0; i < 2; i++) {                    // B: 32 k x 64 n = 512 vec16
            int v = tid + i * 256;
            int k = v >> 4, nc = (v & 15) * 4;
            cp16(Bsb[buf] + k * 68 + nc, Wb + (size_t)(k0 + k) * G4 + n0 + nc);
        }
        cp_commit();
    };

    issue(0, 0);
    for (int kc = 0; kc < 16; kc++) {
        if (kc < 15) { issue(kc + 1, (kc + 1) & 1); cp_wait<1>(); }
        else cp_wait<0>();
        __syncthreads();
        const uint32_t* A = Asb[kc & 1];
        const uint32_t* Bp = Bsb[kc & 1];
#pragma unroll
        for (int kk = 0; kk < 32; kk += 8) wtile_k8(A, Bp, kk, wm, wn, grp, t4, acc);
        __syncthreads();
    }

    // epilogue: add bias, write fp32 xproj
    float* outp = g_xproj + (size_t)(d * (TT * BB) + sIdx * BB) * G4 + n0;
    const float* bias = bias_all + (size_t)(layer * 2 + d) * G4 + n0;
#pragma unroll
    for (int nt = 0; nt < 4; nt++) {
        int col = wn + nt * 8 + 2 * t4;
        float b0 = bias[col], b1 = bias[col + 1];
#pragma unroll
        for (int mt = 0; mt < 2; mt++) {
            int row = wm + mt * 16 + grp;
            float2 v0 = make_float2(acc[mt][nt][0] + b0, acc[mt][nt][1] + b1);
            float2 v1 = make_float2(acc[mt][nt][2] + b0, acc[mt][nt][3] + b1);
            *(float2*)(outp + (size_t)row * G4 + col) = v0;
            *(float2*)(outp + (size_t)(row + 8) * G4 + col) = v1;
        }
    }
}

// ---------------- one recurrence step (both dirs across grid.z) ----------------
// Grid: (32 hidden slices of 16, 2 batch halves of 64, 2 dirs). 128 threads, 4 warps (2Mx2N).
// CTA: gates[64 x (4 gate groups x 16)] = h[64x512] * Wh(gathered 64 cols), then LSTM cell.
__global__ void __launch_bounds__(128) k_scan(int layer, int s, float* __restrict__ out) {
    __shared__ uint32_t sm[8960];                        // 35840 B
    uint32_t* Asb[2] = { sm, sm + 2304 };                // 64*36 each
    uint32_t* Bsb[2] = { sm + 4608, sm + 4608 + 2176 };  // 32*68 each

    const int tid = threadIdx.x, lane = tid & 31, warp = tid >> 5;
    const int grp = lane >> 2, t4 = lane & 3;
    const int wm = (warp & 1) * 32, wn = (warp >> 1) * 32;
    const int d = blockIdx.z, m0 = blockIdx.y * 64, slice = blockIdx.x;
    const int pr = s & 1;                                 // read parity
    const int n16 = slice * 16;

    const uint32_t* hb = g_h + ((size_t)(pr * 2 + d) * BB + m0) * HH;
    const uint32_t* Wb = g_Whtf + (size_t)(layer * 2 + d) * HH * G4;

    float acc[2][4][4];
#pragma unroll
    for (int a = 0; a < 2; a++)
#pragma unroll
        for (int b = 0; b < 4; b++)
#pragma unroll
            for (int c = 0; c < 4; c++) acc[a][b][c] = 0.f;

    auto issue = [&](int kc, int buf) {
        int k0 = kc * 32;
#pragma unroll
        for (int i = 0; i < 4; i++) {                    // A: 64 rows x 32 k = 512 vec16
            int v = tid + i * 128;
            int r = v >> 3, kcol = (v & 7) * 4;
            cp16(Asb[buf] + r * 36 + kcol, hb + (size_t)r * HH + k0 + kcol);
        }
#pragma unroll
        for (int i = 0; i < 4; i++) {                    // B gathered: 32 k x 64 gate cols
            int v = tid + i * 128;
            int k = v >> 4, jc = (v & 15) * 4;
            int gcol = (jc >> 4) * HH + n16 + (jc & 15); // gate group * 512 + slice cols
            cp16(Bsb[buf] + k * 68 + jc, Wb + (size_t)(k0 + k) * G4 + gcol);
        }
        cp_commit();
    };

    issue(0, 0);
    for (int kc = 0; kc < 16; kc++) {
        if (kc < 15) { issue(kc + 1, (kc + 1) & 1); cp_wait<1>(); }
        else cp_wait<0>();
        __syncthreads();
        const uint32_t* A = Asb[kc & 1];
        const uint32_t* Bp = Bsb[kc & 1];
#pragma unroll
        for (int kk = 0; kk < 32; kk += 8) wtile_k8(A, Bp, kk, wm, wn, grp, t4, acc);
        __syncthreads();
    }

    // gate exchange through smem (overwrites A staging; compute fully done)
    float* Gs = reinterpret_cast<float*>(sm);            // 64 x 68
#pragma unroll
    for (int nt = 0; nt < 4; nt++) {
        int col = wn + nt * 8 + 2 * t4;
#pragma unroll
        for (int mt = 0; mt < 2; mt++) {
            int row = wm + mt * 16 + grp;
            Gs[row * 68 + col]           = acc[mt][nt][0];
            Gs[row * 68 + col + 1]       = acc[mt][nt][1];
            Gs[(row + 8) * 68 + col]     = acc[mt][nt][2];
            Gs[(row + 8) * 68 + col + 1] = acc[mt][nt][3];
        }
    }
    __syncthreads();

    // LSTM cell: 64 batch x 16 hidden = 1024 cells, 8 per thread
    for (int idx = tid; idx < 1024; idx += 128) {
        int bl = idx >> 4, jl = idx & 15;
        int bg = m0 + bl, jh = n16 + jl;
        float gi = Gs[bl * 68 + jl];
        float gf = Gs[bl * 68 + jl + 16];
        float gg = Gs[bl * 68 + jl + 32];
        float go = Gs[bl * 68 + jl + 48];
        const float* xp = g_xproj + (size_t)(d * (TT * BB) + s * BB + bg) * G4 + jh;
        gi += xp[0];
        gf += xp[512];
        gg += xp[1024];
        go += xp[1536];
        float iv = 1.f / (1.f + expf(-gi));
        float fv = 1.f / (1.f + expf(-gf));
        float gv = tanhf(gg);
        float ov = 1.f / (1.f + expf(-go));
        size_t ci = ((size_t)d * BB + bg) * HH + jh;
        float cn = fv * g_c[ci] + iv * gv;
        float hn = ov * tanhf(cn);
        g_c[ci] = cn;
        g_h[((size_t)((pr ^ 1) * 2 + d) * BB + bg) * HH + jh] = f2tf(hn);
        if (layer == 0) {
            g_hbuf[((size_t)(d * (TT * BB) + s * BB + bg)) * HH + jh] = f2tf(hn);
        } else {
            int t = d ? (TT - 1 - s) : s;
            out[((size_t)bg * TT + t) * (2 * HH) + d * HH + jh] = hn;
        }
    }
}

// ---------------- launch ----------------
extern "C" void kernel_launch(void* const* d_in, const int* in_sizes, int n_in,
                              void* d_out, int out_size) {
    const float* x    = (const float*)d_in[0];
    const float* Wx   = (const float*)d_in[1];
    const float* Wh   = (const float*)d_in[2];
    const float* bias = (const float*)d_in[3];
    float* out = (float*)d_out;

    cudaFuncSetAttribute(k_proj, cudaFuncAttributeMaxDynamicSharedMemorySize, 56 * 1024);

    k_preconvert<<<1024, 256>>>(x, Wx, Wh);
    for (int l = 0; l < 2; l++) {
        k_proj<<<dim3(32, 256, 2), 256, 54272>>>(l, bias);
        k_zero<<<512, 256>>>();
        for (int s = 0; s < TT; s++) {
            k_scan<<<dim3(32, 2, 2), 128>>>(l, s, out);
        }
    }
}

// round 9
// speedup vs baseline: 1.1641x; 1.1641x over previous
#include <cuda_runtime.h>
#include <cuda_bf16.h>
#include <math.h>
#include <stdint.h>

// Problem sizes
#define BB   128
#define TT   256
#define HH   512
#define G4   2048   // 4*H
#define NCTA 128    // persistent scan grid (<=148 SMs, 1 CTA/SM => co-resident)

// ---------------- scratch (static device memory; no allocations) ----------------
__device__ uint32_t g_xtf[(size_t)BB * TT * HH];              // x in tf32, [b][t][h]
__device__ uint32_t g_Wxtf[(size_t)2 * 2 * HH * G4];          // [l][d][k][n] tf32
__device__ uint32_t g_Whtf[(size_t)2 * 2 * HH * G4];          // [l][d][k][n] tf32
__device__ float    g_xproj[(size_t)2 * TT * BB * G4];        // [d][s][b][gate] fp32
__device__ uint32_t g_hbuf[(size_t)2 * TT * BB * HH];         // layer0 h out, tf32, [d][s][b][j]
__device__ uint32_t g_h[(size_t)2 * 2 * BB * HH];             // [parity][d][b][j] tf32

// grid barrier state (persists across launches/replays; gen is monotonic,
// count always returns to 0 after每 barrier completes)
__device__ unsigned g_bar_count;
__device__ unsigned g_bar_gen;

// ---------------- helpers ----------------
__device__ __forceinline__ uint32_t f2tf(float x) {
    uint32_t r;
    asm("cvt.rna.tf32.f32 %0, %1;" : "=r"(r) : "f"(x));
    return r;
}

__device__ __forceinline__ void mma_tf32(float acc[4], const uint32_t a[4], const uint32_t b[2]) {
    asm volatile(
        "mma.sync.aligned.m16n8k8.row.col.f32.tf32.tf32.f32 "
        "{%0,%1,%2,%3}, {%4,%5,%6,%7}, {%8,%9}, {%0,%1,%2,%3};\n"
        : "+f"(acc[0]), "+f"(acc[1]), "+f"(acc[2]), "+f"(acc[3])
        : "r"(a[0]), "r"(a[1]), "r"(a[2]), "r"(a[3]), "r"(b[0]), "r"(b[1]));
}

__device__ __forceinline__ void cp16(uint32_t* smem_ptr, const void* gptr) {
    uint32_t s = (uint32_t)__cvta_generic_to_shared(smem_ptr);
    asm volatile("cp.async.cg.shared.global [%0], [%1], 16;\n" :: "r"(s), "l"(gptr));
}
__device__ __forceinline__ void cp_commit() { asm volatile("cp.async.commit_group;\n"); }
template <int N>
__device__ __forceinline__ void cp_wait() { asm volatile("cp.async.wait_group %0;\n" :: "n"(N)); }

// Warp tile 32x32, one k8 slab. SA/SB = smem row strides (words) for A/B.
template <int SA, int SB>
__device__ __forceinline__ void wtile_k8(const uint32_t* __restrict__ As,
                                         const uint32_t* __restrict__ Bs,
                                         int kk, int wm, int wn, int grp, int t4,
                                         float acc[2][4][4]) {
    uint32_t a[2][4], bf[4][2];
#pragma unroll
    for (int mt = 0; mt < 2; mt++) {
        const uint32_t* Ar = As + (wm + mt * 16 + grp) * SA + kk + t4;
        a[mt][0] = Ar[0];
        a[mt][1] = Ar[8 * SA];
        a[mt][2] = Ar[4];
        a[mt][3] = Ar[8 * SA + 4];
    }
#pragma unroll
    for (int nt = 0; nt < 4; nt++) {
        const uint32_t* Br = Bs + (kk + t4) * SB + wn + nt * 8 + grp;
        bf[nt][0] = Br[0];
        bf[nt][1] = Br[4 * SB];
    }
#pragma unroll
    for (int mt = 0; mt < 2; mt++)
#pragma unroll
        for (int nt = 0; nt < 4; nt++) mma_tf32(acc[mt][nt], a[mt], bf[nt]);
}

// ---------------- pre-convert fp32 -> tf32 ----------------
__global__ void k_preconvert(const float* __restrict__ x,
                             const float* __restrict__ Wx,
                             const float* __restrict__ Wh) {
    int stride = gridDim.x * blockDim.x;
    int i0 = blockIdx.x * blockDim.x + threadIdx.x;
    for (int i = i0; i < BB * TT * HH; i += stride) g_xtf[i] = f2tf(x[i]);
    for (int i = i0; i < 2 * 2 * HH * G4; i += stride) {
        g_Wxtf[i] = f2tf(Wx[i]);
        g_Whtf[i] = f2tf(Wh[i]);
    }
}

// ---------------- zero h(parity0) ----------------
__global__ void k_zero() {
    int i = blockIdx.x * blockDim.x + threadIdx.x;
    if (i < 2 * BB * HH) g_h[i] = 0u;   // parity 0 block
}

// ---------------- input projection: xproj = A * Wx + bias ----------------
// Grid: (32 n-tiles of 64, 256 s, 2 dirs). 256 threads, 8 warps (4M x 2N).
__global__ void __launch_bounds__(256) k_proj(int layer, const float* __restrict__ bias_all) {
    extern __shared__ uint32_t smp[];
    uint32_t* Asb[2] = { smp, smp + 4608 };             // 128*36 each
    uint32_t* Bsb[2] = { smp + 9216, smp + 11392 };     // 32*68 each

    const int tid = threadIdx.x, lane = tid & 31, warp = tid >> 5;
    const int grp = lane >> 2, t4 = lane & 3;
    const int wm = (warp & 3) * 32, wn = (warp >> 2) * 32;
    const int d = blockIdx.z, sIdx = blockIdx.y, n0 = blockIdx.x * 64;
    const int t_act = d ? (TT - 1 - sIdx) : sIdx;

    const uint32_t* Wb = g_Wxtf + ((size_t)(layer * 2 + d) * HH) * G4;

    float acc[2][4][4];
#pragma unroll
    for (int a = 0; a < 2; a++)
#pragma unroll
        for (int b = 0; b < 4; b++)
#pragma unroll
            for (int c = 0; c < 4; c++) acc[a][b][c] = 0.f;

    auto issue = [&](int kc, int buf) {
        int k0 = kc * 32;
#pragma unroll
        for (int i = 0; i < 4; i++) {                    // A: 128 rows x 32 k
            int v = tid + i * 256;
            int r = v >> 3, kcol = (v & 7) * 4;
            const uint32_t* src;
            if (layer == 0)
                src = g_xtf + ((size_t)r * TT + t_act) * HH + k0 + kcol;
            else
                src = g_hbuf + ((size_t)(d * (TT * BB) + sIdx * BB + r)) * HH + k0 + kcol;
            cp16(Asb[buf] + r * 36 + kcol, src);
        }
#pragma unroll
        for (int i = 0; i < 2; i++) {                    // B: 32 k x 64 n
            int v = tid + i * 256;
            int k = v >> 4, nc = (v & 15) * 4;
            cp16(Bsb[buf] + k * 68 + nc, Wb + (size_t)(k0 + k) * G4 + n0 + nc);
        }
        cp_commit();
    };

    issue(0, 0);
    for (int kc = 0; kc < 16; kc++) {
        if (kc < 15) { issue(kc + 1, (kc + 1) & 1); cp_wait<1>(); }
        else cp_wait<0>();
        __syncthreads();
        const uint32_t* A = Asb[kc & 1];
        const uint32_t* Bp = Bsb[kc & 1];
#pragma unroll
        for (int kk = 0; kk < 32; kk += 8) wtile_k8<36, 68>(A, Bp, kk, wm, wn, grp, t4, acc);
        __syncthreads();
    }

    float* outp = g_xproj + (size_t)(d * (TT * BB) + sIdx * BB) * G4 + n0;
    const float* bias = bias_all + (size_t)(layer * 2 + d) * G4 + n0;
#pragma unroll
    for (int nt = 0; nt < 4; nt++) {
        int col = wn + nt * 8 + 2 * t4;
        float b0 = bias[col], b1 = bias[col + 1];
#pragma unroll
        for (int mt = 0; mt < 2; mt++) {
            int row = wm + mt * 16 + grp;
            float2 v0 = make_float2(acc[mt][nt][0] + b0, acc[mt][nt][1] + b1);
            float2 v1 = make_float2(acc[mt][nt][2] + b0, acc[mt][nt][3] + b1);
            *(float2*)(outp + (size_t)row * G4 + col) = v0;
            *(float2*)(outp + (size_t)(row + 8) * G4 + col) = v1;
        }
    }
}

// ---------------- persistent recurrence scan ----------------
// 128 CTAs (32 hidden slices x 2 batch halves x 2 dirs), 128 threads (4 warps, 2Mx2N).
// Wh slice (512k x 64 gathered gate cols) resident in smem for all 256 steps.
// Per step: gates[64b x 64g] = h[64x512] @ WhS, fused LSTM cell, h -> L2, grid barrier.
__global__ void __launch_bounds__(128) k_scan_persist(int layer, float* __restrict__ out) {
    extern __shared__ uint32_t sm[];
    uint32_t* WhS = sm;                                  // 512*72 = 36864 words
    uint32_t* Asb[2] = { sm + 36864, sm + 36864 + 4352 };// 64*68 each
    float* Gs = (float*)(sm + 36864 + 8704);             // 64*68 floats

    const int tid = threadIdx.x, lane = tid & 31, warp = tid >> 5;
    const int grp = lane >> 2, t4 = lane & 3;
    const int wm = (warp & 1) * 32, wn = (warp >> 1) * 32;
    const int bid = blockIdx.x;
    const int d = bid & 1, mh = (bid >> 1) & 1, slice = bid >> 2;
    const int m0 = mh * 64, n16 = slice * 16;

    // Load resident Wh slice (gathered gate layout), once per layer.
    const uint32_t* Wb = g_Whtf + (size_t)(layer * 2 + d) * HH * G4;
    for (int v = tid; v < 512 * 16; v += 128) {          // 8192 vec4 loads
        int k = v >> 4, jc = (v & 15) * 4;
        int gcol = (jc >> 4) * HH + n16 + (jc & 15);
        cp16(WhS + k * 72 + jc, Wb + (size_t)k * G4 + gcol);
    }
    cp_commit(); cp_wait<0>();

    unsigned my_gen = 0;
    if (tid == 0) my_gen = *(volatile unsigned*)&g_bar_gen;  // entry gen (pre-barrier-1)

    float creg[8];
#pragma unroll
    for (int i = 0; i < 8; i++) creg[i] = 0.f;

    __syncthreads();

    for (int s = 0; s < TT; s++) {
        const int pr = s & 1;
        const uint32_t* hb = g_h + ((size_t)(pr * 2 + d) * BB + m0) * HH;

        auto issue = [&](int kc, int buf) {
            int k0 = kc * 64;
#pragma unroll
            for (int i = 0; i < 8; i++) {                // A: 64 rows x 64 k
                int v = tid + i * 128;
                int r = v >> 4, kcol = (v & 15) * 4;
                cp16(Asb[buf] + r * 68 + kcol, hb + (size_t)r * HH + k0 + kcol);
            }
            cp_commit();
        };

        float acc[2][4][4];
#pragma unroll
        for (int a = 0; a < 2; a++)
#pragma unroll
            for (int b = 0; b < 4; b++)
#pragma unroll
                for (int c = 0; c < 4; c++) acc[a][b][c] = 0.f;

        issue(0, 0);
        for (int kc = 0; kc < 8; kc++) {
            if (kc < 7) { issue(kc + 1, (kc + 1) & 1); cp_wait<1>(); }
            else cp_wait<0>();
            __syncthreads();
            const uint32_t* A = Asb[kc & 1];
            const uint32_t* Bp = WhS + kc * 64 * 72;
#pragma unroll
            for (int kk = 0; kk < 64; kk += 8) wtile_k8<68, 72>(A, Bp, kk, wm, wn, grp, t4, acc);
            __syncthreads();
        }

        // gate exchange through smem
#pragma unroll
        for (int nt = 0; nt < 4; nt++) {
            int col = wn + nt * 8 + 2 * t4;
#pragma unroll
            for (int mt = 0; mt < 2; mt++) {
                int row = wm + mt * 16 + grp;
                Gs[row * 68 + col]           = acc[mt][nt][0];
                Gs[row * 68 + col + 1]       = acc[mt][nt][1];
                Gs[(row + 8) * 68 + col]     = acc[mt][nt][2];
                Gs[(row + 8) * 68 + col + 1] = acc[mt][nt][3];
            }
        }
        __syncthreads();

        // LSTM cell: 1024 cells, 8/thread; c stays in registers (exclusive ownership).
#pragma unroll
        for (int i = 0; i < 8; i++) {
            int idx = tid + i * 128;
            int bl = idx >> 4, jl = idx & 15;
            int bg = m0 + bl, jh = n16 + jl;
            const float* xp = g_xproj + (size_t)(d * (TT * BB) + s * BB + bg) * G4 + jh;
            float gi = Gs[bl * 68 + jl]      + __ldcg(xp);
            float gf = Gs[bl * 68 + jl + 16] + __ldcg(xp + 512);
            float gg = Gs[bl * 68 + jl + 32] + __ldcg(xp + 1024);
            float go = Gs[bl * 68 + jl + 48] + __ldcg(xp + 1536);
            float iv = 1.f / (1.f + expf(-gi));
            float fv = 1.f / (1.f + expf(-gf));
            float gv = tanhf(gg);
            float ov = 1.f / (1.f + expf(-go));
            float cn = fv * creg[i] + iv * gv;
            float hn = ov * tanhf(cn);
            creg[i] = cn;
            // h for next step: L2-only store (L1 is stale-prone in a persistent kernel)
            __stcg((unsigned int*)&g_h[((size_t)((pr ^ 1) * 2 + d) * BB + bg) * HH + jh], f2tf(hn));
            if (layer == 0) {
                __stcg((unsigned int*)&g_hbuf[((size_t)(d * (TT * BB) + s * BB + bg)) * HH + jh], f2tf(hn));
            } else {
                int t = d ? (TT - 1 - s) : s;
                out[((size_t)bg * TT + t) * (2 * HH) + d * HH + jh] = hn;
            }
        }

        // grid barrier (skip after last step; state stays consistent)
        if (s < TT - 1) {
            __syncthreads();
            if (tid == 0) {
                __threadfence();
                my_gen++;
                unsigned prev = atomicAdd(&g_bar_count, 1);
                if (prev == NCTA - 1) {
                    g_bar_count = 0;          // peers are spinning on gen, not count
                    __threadfence();
                    atomicExch(&g_bar_gen, my_gen);
                } else {
                    while (*(volatile unsigned*)&g_bar_gen != my_gen) __nanosleep(32);
                    __threadfence();
                }
            }
            __syncthreads();
        }
    }
}

// ---------------- launch ----------------
extern "C" void kernel_launch(void* const* d_in, const int* in_sizes, int n_in,
                              void* d_out, int out_size) {
    const float* x    = (const float*)d_in[0];
    const float* Wx   = (const float*)d_in[1];
    const float* Wh   = (const float*)d_in[2];
    const float* bias = (const float*)d_in[3];
    float* out = (float*)d_out;

    cudaFuncSetAttribute(k_proj, cudaFuncAttributeMaxDynamicSharedMemorySize, 56 * 1024);
    cudaFuncSetAttribute(k_scan_persist, cudaFuncAttributeMaxDynamicSharedMemorySize, 200704);

    k_preconvert<<<1024, 256>>>(x, Wx, Wh);
    for (int l = 0; l < 2; l++) {
        k_proj<<<dim3(32, 256, 2), 256, 54272>>>(l, bias);
        k_zero<<<512, 256>>>();
        k_scan_persist<<<NCTA, 128, 199680>>>(l, out);
    }
}